// round 1
// baseline (speedup 1.0000x reference)
#include <cuda_runtime.h>
#include <cstdint>

// Problem constants (fixed by the benchmark shapes)
#define DIN   768     // input feature dim (3*H)
#define DHID  384     // hidden dim
#define NH    256     // number of harmonics H
#define KTOP  128     // top-k
#define BM    64      // rows per CTA
#define BK    16      // k-chunk

// Scratch for h_act = silu(LN(wave@W1+b1)) : 32768 x 384 fp32 (~50 MB)
__device__ float g_h[8 * 4096 * DHID];

static __device__ __forceinline__ unsigned f2key(float f) {
    unsigned u = __float_as_uint(f);
    return (u & 0x80000000u) ? ~u : (u | 0x80000000u);  // monotone float->uint
}

// ---------------------------------------------------------------------------
// Kernel 1: h = silu(layernorm(wave @ W1 + b1))  -> g_h
// CTA: 64 rows x 384 cols (full DH), 384 threads, 8x8 thread tiles.
// Thread (ty,tx): rows ty*8..+7, cols {tx*4..+3} and {192+tx*4..+3}
// ---------------------------------------------------------------------------
__global__ void __launch_bounds__(384) k_mlp1(
    const float* __restrict__ wave, const float* __restrict__ W1,
    const float* __restrict__ b1,   const float* __restrict__ lng,
    const float* __restrict__ lnb,  int rows)
{
    __shared__ float sA[BK][BM];      // [k][row]
    __shared__ float sB[BK][DHID];    // [k][col]; reused as reduction buffer
    __shared__ float sMu[BM];
    __shared__ float sRs[BM];

    const int tid  = threadIdx.x;
    const int ty   = tid / 48;
    const int tx   = tid - ty * 48;
    const int colL = tx * 4;
    const int colH = 192 + tx * 4;
    const int rowBase = blockIdx.x * BM;

    float acc[8][8];
#pragma unroll
    for (int r = 0; r < 8; r++)
#pragma unroll
        for (int c = 0; c < 8; c++) acc[r][c] = 0.f;

    for (int k0 = 0; k0 < DIN; k0 += BK) {
        for (int idx = tid; idx < BM * BK; idx += 384) {
            int kk = idx & (BK - 1);
            int r  = idx >> 4;
            int row = rowBase + r;
            sA[kk][r] = (row < rows) ? __ldg(&wave[(size_t)row * DIN + (k0 + kk)]) : 0.f;
        }
        for (int idx = tid; idx < BK * DHID; idx += 384) {
            int kk = idx / DHID;
            int c  = idx - kk * DHID;
            sB[kk][c] = __ldg(&W1[(size_t)(k0 + kk) * DHID + c]);
        }
        __syncthreads();
#pragma unroll
        for (int kk = 0; kk < BK; kk++) {
            float a[8], b[8];
            *(float4*)&a[0] = *(const float4*)&sA[kk][ty * 8];
            *(float4*)&a[4] = *(const float4*)&sA[kk][ty * 8 + 4];
            *(float4*)&b[0] = *(const float4*)&sB[kk][colL];
            *(float4*)&b[4] = *(const float4*)&sB[kk][colH];
#pragma unroll
            for (int r = 0; r < 8; r++)
#pragma unroll
                for (int c = 0; c < 8; c++)
                    acc[r][c] = fmaf(a[r], b[c], acc[r][c]);
        }
        __syncthreads();
    }

    // Per-thread column params
    float bc[8], gc[8], bb[8];
    *(float4*)&bc[0] = *(const float4*)&b1[colL];
    *(float4*)&bc[4] = *(const float4*)&b1[colH];
    *(float4*)&gc[0] = *(const float4*)&lng[colL];
    *(float4*)&gc[4] = *(const float4*)&lng[colH];
    *(float4*)&bb[0] = *(const float4*)&lnb[colL];
    *(float4*)&bb[4] = *(const float4*)&lnb[colH];

#pragma unroll
    for (int r = 0; r < 8; r++)
#pragma unroll
        for (int c = 0; c < 8; c++) acc[r][c] += bc[c];

    float* red = &sB[0][0];   // 64 x 48 (stride 49) partial sums; fits in sB

    // Pass 1: mean
#pragma unroll
    for (int r = 0; r < 8; r++) {
        float s = 0.f;
#pragma unroll
        for (int c = 0; c < 8; c++) s += acc[r][c];
        red[(ty * 8 + r) * 49 + tx] = s;
    }
    __syncthreads();
    if (tid < BM) {
        float s = 0.f;
        for (int i = 0; i < 48; i++) s += red[tid * 49 + i];
        sMu[tid] = s * (1.0f / DHID);
    }
    __syncthreads();
    float mu[8];
#pragma unroll
    for (int r = 0; r < 8; r++) mu[r] = sMu[ty * 8 + r];

    // Pass 2: variance
#pragma unroll
    for (int r = 0; r < 8; r++) {
        float s = 0.f;
#pragma unroll
        for (int c = 0; c < 8; c++) {
            float d = acc[r][c] - mu[r];
            s = fmaf(d, d, s);
        }
        red[(ty * 8 + r) * 49 + tx] = s;
    }
    __syncthreads();
    if (tid < BM) {
        float s = 0.f;
        for (int i = 0; i < 48; i++) s += red[tid * 49 + i];
        sRs[tid] = rsqrtf(s * (1.0f / DHID) + 1e-5f);
    }
    __syncthreads();

#pragma unroll
    for (int r = 0; r < 8; r++) {
        int row = rowBase + ty * 8 + r;
        if (row >= rows) continue;
        float rs = sRs[ty * 8 + r];
        float o[8];
#pragma unroll
        for (int c = 0; c < 8; c++) {
            float x = (acc[r][c] - mu[r]) * rs * gc[c] + bb[c];
            o[c] = x / (1.0f + expf(-x));   // silu
        }
        float* dst = &g_h[(size_t)row * DHID];
        *(float4*)&dst[colL] = *(float4*)&o[0];
        *(float4*)&dst[colH] = *(float4*)&o[4];
    }
}

// ---------------------------------------------------------------------------
// Kernel 2: scores = h @ W2 + b2, fused perturb + exact top-128 + masked write
// CTA: 64 rows x 256 cols (full H), 256 threads. warp == ty, owns rows ty*8..+7
// Thread (ty,tx): cols {tx*4..+3} and {128+tx*4..+3}
// ---------------------------------------------------------------------------
__global__ void __launch_bounds__(256) k_mlp2(
    const float* __restrict__ W2,  const float* __restrict__ b2,
    const float* __restrict__ wave, const float* __restrict__ gu,
    float* __restrict__ out, int rows)
{
    __shared__ float sA[BK][BM];
    __shared__ float sB[BK][NH];

    const int tid  = threadIdx.x;
    const int ty   = tid >> 5;      // warp id
    const int tx   = tid & 31;      // lane id
    const int colL = tx * 4;
    const int colH = 128 + tx * 4;
    const int rowBase = blockIdx.x * BM;

    float acc[8][8];
#pragma unroll
    for (int r = 0; r < 8; r++)
#pragma unroll
        for (int c = 0; c < 8; c++) acc[r][c] = 0.f;

    for (int k0 = 0; k0 < DHID; k0 += BK) {
        for (int idx = tid; idx < BM * BK; idx += 256) {
            int kk = idx & (BK - 1);
            int r  = idx >> 4;
            int row = rowBase + r;
            sA[kk][r] = (row < rows) ? g_h[(size_t)row * DHID + (k0 + kk)] : 0.f;
        }
        for (int idx = tid; idx < BK * NH; idx += 256) {
            int kk = idx >> 8;
            int c  = idx & (NH - 1);
            sB[kk][c] = __ldg(&W2[(size_t)(k0 + kk) * NH + c]);
        }
        __syncthreads();
#pragma unroll
        for (int kk = 0; kk < BK; kk++) {
            float a[8], b[8];
            *(float4*)&a[0] = *(const float4*)&sA[kk][ty * 8];
            *(float4*)&a[4] = *(const float4*)&sA[kk][ty * 8 + 4];
            *(float4*)&b[0] = *(const float4*)&sB[kk][colL];
            *(float4*)&b[4] = *(const float4*)&sB[kk][colH];
#pragma unroll
            for (int r = 0; r < 8; r++)
#pragma unroll
                for (int c = 0; c < 8; c++)
                    acc[r][c] = fmaf(a[r], b[c], acc[r][c]);
        }
        __syncthreads();
    }

    float b2c[8];
    *(float4*)&b2c[0] = *(const float4*)&b2[colL];
    *(float4*)&b2c[4] = *(const float4*)&b2[colH];
#pragma unroll
    for (int r = 0; r < 8; r++)
#pragma unroll
        for (int c = 0; c < 8; c++) acc[r][c] += b2c[c];

    const unsigned FULL = 0xffffffffu;
    const unsigned lowmask = (1u << tx) - 1u;

#pragma unroll 1
    for (int r = 0; r < 8; r++) {
        int row = rowBase + ty * 8 + r;     // warp-uniform
        if (row >= rows) continue;
        const float* wrow = wave + (size_t)row * DIN;

        // amps + row amp-sum
        float amp[8];
        *(float4*)&amp[0] = *(const float4*)&wrow[NH + colL];
        *(float4*)&amp[4] = *(const float4*)&wrow[NH + colH];
        float s = 0.f;
#pragma unroll
        for (int j = 0; j < 8; j++) s += amp[j];
#pragma unroll
        for (int o = 16; o; o >>= 1) s += __shfl_xor_sync(FULL, s, o);
        float inv = 1.0f / (s + 1e-8f);

        // gumbel + perturbed keys
        float gub[8];
        *(float4*)&gub[0] = *(const float4*)&gu[(size_t)row * NH + colL];
        *(float4*)&gub[4] = *(const float4*)&gu[(size_t)row * NH + colH];
        unsigned key[8];
        float vbuf[8];
#pragma unroll
        for (int j = 0; j < 8; j++) {
            float t = -logf(gub[j] + 1e-8f);
            float g = -logf(t + 1e-8f);
            float v = acc[r][j] + amp[j] * inv + g;   // TEMP == 1
            vbuf[j] = v;
            key[j] = f2key(v);
        }
        (void)vbuf;

        // exact 128-th largest key via MSB-first radix select (warp-wide)
        unsigned prefix = 0;
        int want = KTOP;
#pragma unroll 1
        for (int bit = 31; bit >= 0; --bit) {
            unsigned tgt = (prefix >> bit) | 1u;
            int c = 0;
#pragma unroll
            for (int j = 0; j < 8; j++) c += ((key[j] >> bit) == tgt);
            c = __reduce_add_sync(FULL, c);
            if (c >= want) prefix |= (1u << bit);
            else           want -= c;
        }
        const unsigned T = prefix;

        // selection with JAX tie-break (lowest index first among equals)
        int mygt = 0;
#pragma unroll
        for (int j = 0; j < 8; j++) mygt += (key[j] > T);
        int need_eq = KTOP - __reduce_add_sync(FULL, mygt);

        unsigned bal[8];
#pragma unroll
        for (int j = 0; j < 8; j++) bal[j] = __ballot_sync(FULL, key[j] == T);

        int low_lower = 0, low_total = 0, high_lower = 0;
#pragma unroll
        for (int j = 0; j < 4; j++) {
            low_lower += __popc(bal[j] & lowmask);
            low_total += __popc(bal[j]);
        }
#pragma unroll
        for (int j = 4; j < 8; j++) high_lower += __popc(bal[j] & lowmask);

        bool sel[8];
        int prev = 0;
#pragma unroll
        for (int j = 0; j < 4; j++) {           // low-half indices tx*4+j
            int e = (bal[j] >> tx) & 1;
            sel[j] = (key[j] > T) || (e && (low_lower + prev) < need_eq);
            prev += e;
        }
        prev = 0;
#pragma unroll
        for (int j = 4; j < 8; j++) {           // high-half indices 128+tx*4+(j-4)
            int e = (bal[j] >> tx) & 1;
            sel[j] = (key[j] > T) || (e && (low_total + high_lower + prev) < need_eq);
            prev += e;
        }

        // masked write: out = [freqs*m, amps*m, phases*m]
        float fr[8], ph[8];
        *(float4*)&fr[0] = *(const float4*)&wrow[colL];
        *(float4*)&fr[4] = *(const float4*)&wrow[colH];
        *(float4*)&ph[0] = *(const float4*)&wrow[2 * NH + colL];
        *(float4*)&ph[4] = *(const float4*)&wrow[2 * NH + colH];

        float of[8], oa[8], op[8];
#pragma unroll
        for (int j = 0; j < 8; j++) {
            float m = sel[j] ? 1.0f : 0.0f;
            of[j] = fr[j] * m;
            oa[j] = amp[j] * m;
            op[j] = ph[j] * m;
        }
        float* orow = out + (size_t)row * DIN;
        *(float4*)&orow[colL]          = *(float4*)&of[0];
        *(float4*)&orow[colH]          = *(float4*)&of[4];
        *(float4*)&orow[NH + colL]     = *(float4*)&oa[0];
        *(float4*)&orow[NH + colH]     = *(float4*)&oa[4];
        *(float4*)&orow[2 * NH + colL] = *(float4*)&op[0];
        *(float4*)&orow[2 * NH + colH] = *(float4*)&op[4];
    }
}

// ---------------------------------------------------------------------------
extern "C" void kernel_launch(void* const* d_in, const int* in_sizes, int n_in,
                              void* d_out, int out_size)
{
    const float* wave = (const float*)d_in[0];
    const float* gu   = (const float*)d_in[1];
    const float* W1   = (const float*)d_in[2];
    const float* b1   = (const float*)d_in[3];
    const float* lng  = (const float*)d_in[4];
    const float* lnb  = (const float*)d_in[5];
    const float* W2   = (const float*)d_in[6];
    const float* b2   = (const float*)d_in[7];
    float* out = (float*)d_out;

    int rows = in_sizes[0] / DIN;           // 32768
    int nb   = (rows + BM - 1) / BM;        // 512

    k_mlp1<<<nb, 384>>>(wave, W1, b1, lng, lnb, rows);
    k_mlp2<<<nb, 256>>>(W2, b2, wave, gu, out, rows);
}

// round 2
// speedup vs baseline: 1.0006x; 1.0006x over previous
#include <cuda_runtime.h>
#include <cstdint>

// Problem constants (fixed by the benchmark shapes)
#define DIN   768     // input feature dim (3*H)
#define DHID  384     // hidden dim
#define NH    256     // number of harmonics H
#define KTOP  128     // top-k
#define BM    64      // rows per CTA
#define BK    16      // k-chunk

// Scratch for h_act = silu(LN(wave@W1+b1)) : 32768 x 384 fp32 (~50 MB)
__device__ float g_h[8 * 4096 * DHID];

static __device__ __forceinline__ unsigned f2key(float f) {
    unsigned u = __float_as_uint(f);
    return (u & 0x80000000u) ? ~u : (u | 0x80000000u);  // monotone float->uint
}

// ---------------------------------------------------------------------------
// Kernel 1: h = silu(layernorm(wave @ W1 + b1))  -> g_h
// CTA: 64 rows x 384 cols (full DH), 384 threads, 8x8 thread tiles.
// Thread (ty,tx): rows ty*8..+7, cols {tx*4..+3} and {192+tx*4..+3}
// ---------------------------------------------------------------------------
__global__ void __launch_bounds__(384) k_mlp1(
    const float* __restrict__ wave, const float* __restrict__ W1,
    const float* __restrict__ b1,   const float* __restrict__ lng,
    const float* __restrict__ lnb,  int rows)
{
    __shared__ float sA[BK][BM];      // [k][row]
    __shared__ float sB[BK][DHID];    // [k][col]; reused as reduction buffer
    __shared__ float sMu[BM];
    __shared__ float sRs[BM];

    const int tid  = threadIdx.x;
    const int ty   = tid / 48;
    const int tx   = tid - ty * 48;
    const int colL = tx * 4;
    const int colH = 192 + tx * 4;
    const int rowBase = blockIdx.x * BM;

    float acc[8][8];
#pragma unroll
    for (int r = 0; r < 8; r++)
#pragma unroll
        for (int c = 0; c < 8; c++) acc[r][c] = 0.f;

    for (int k0 = 0; k0 < DIN; k0 += BK) {
        for (int idx = tid; idx < BM * BK; idx += 384) {
            int kk = idx & (BK - 1);
            int r  = idx >> 4;
            int row = rowBase + r;
            sA[kk][r] = (row < rows) ? __ldg(&wave[(size_t)row * DIN + (k0 + kk)]) : 0.f;
        }
        for (int idx = tid; idx < BK * DHID; idx += 384) {
            int kk = idx / DHID;
            int c  = idx - kk * DHID;
            sB[kk][c] = __ldg(&W1[(size_t)(k0 + kk) * DHID + c]);
        }
        __syncthreads();
#pragma unroll
        for (int kk = 0; kk < BK; kk++) {
            float a[8], b[8];
            *(float4*)&a[0] = *(const float4*)&sA[kk][ty * 8];
            *(float4*)&a[4] = *(const float4*)&sA[kk][ty * 8 + 4];
            *(float4*)&b[0] = *(const float4*)&sB[kk][colL];
            *(float4*)&b[4] = *(const float4*)&sB[kk][colH];
#pragma unroll
            for (int r = 0; r < 8; r++)
#pragma unroll
                for (int c = 0; c < 8; c++)
                    acc[r][c] = fmaf(a[r], b[c], acc[r][c]);
        }
        __syncthreads();
    }

    // Per-thread column params
    float bc[8], gc[8], bb[8];
    *(float4*)&bc[0] = *(const float4*)&b1[colL];
    *(float4*)&bc[4] = *(const float4*)&b1[colH];
    *(float4*)&gc[0] = *(const float4*)&lng[colL];
    *(float4*)&gc[4] = *(const float4*)&lng[colH];
    *(float4*)&bb[0] = *(const float4*)&lnb[colL];
    *(float4*)&bb[4] = *(const float4*)&lnb[colH];

#pragma unroll
    for (int r = 0; r < 8; r++)
#pragma unroll
        for (int c = 0; c < 8; c++) acc[r][c] += bc[c];

    float* red = &sB[0][0];   // 64 x 48 (stride 49) partial sums; fits in sB

    // Pass 1: mean
#pragma unroll
    for (int r = 0; r < 8; r++) {
        float s = 0.f;
#pragma unroll
        for (int c = 0; c < 8; c++) s += acc[r][c];
        red[(ty * 8 + r) * 49 + tx] = s;
    }
    __syncthreads();
    if (tid < BM) {
        float s = 0.f;
        for (int i = 0; i < 48; i++) s += red[tid * 49 + i];
        sMu[tid] = s * (1.0f / DHID);
    }
    __syncthreads();
    float mu[8];
#pragma unroll
    for (int r = 0; r < 8; r++) mu[r] = sMu[ty * 8 + r];

    // Pass 2: variance
#pragma unroll
    for (int r = 0; r < 8; r++) {
        float s = 0.f;
#pragma unroll
        for (int c = 0; c < 8; c++) {
            float d = acc[r][c] - mu[r];
            s = fmaf(d, d, s);
        }
        red[(ty * 8 + r) * 49 + tx] = s;
    }
    __syncthreads();
    if (tid < BM) {
        float s = 0.f;
        for (int i = 0; i < 48; i++) s += red[tid * 49 + i];
        sRs[tid] = rsqrtf(s * (1.0f / DHID) + 1e-5f);
    }
    __syncthreads();

#pragma unroll
    for (int r = 0; r < 8; r++) {
        int row = rowBase + ty * 8 + r;
        if (row >= rows) continue;
        float rs = sRs[ty * 8 + r];
        float o[8];
#pragma unroll
        for (int c = 0; c < 8; c++) {
            float x = (acc[r][c] - mu[r]) * rs * gc[c] + bb[c];
            o[c] = x / (1.0f + expf(-x));   // silu
        }
        float* dst = &g_h[(size_t)row * DHID];
        *(float4*)&dst[colL] = *(float4*)&o[0];
        *(float4*)&dst[colH] = *(float4*)&o[4];
    }
}

// ---------------------------------------------------------------------------
// Kernel 2: scores = h @ W2 + b2, fused perturb + exact top-128 + masked write
// CTA: 64 rows x 256 cols (full H), 256 threads. warp == ty, owns rows ty*8..+7
// Thread (ty,tx): cols {tx*4..+3} and {128+tx*4..+3}
// ---------------------------------------------------------------------------
__global__ void __launch_bounds__(256) k_mlp2(
    const float* __restrict__ W2,  const float* __restrict__ b2,
    const float* __restrict__ wave, const float* __restrict__ gu,
    float* __restrict__ out, int rows)
{
    __shared__ float sA[BK][BM];
    __shared__ float sB[BK][NH];

    const int tid  = threadIdx.x;
    const int ty   = tid >> 5;      // warp id
    const int tx   = tid & 31;      // lane id
    const int colL = tx * 4;
    const int colH = 128 + tx * 4;
    const int rowBase = blockIdx.x * BM;

    float acc[8][8];
#pragma unroll
    for (int r = 0; r < 8; r++)
#pragma unroll
        for (int c = 0; c < 8; c++) acc[r][c] = 0.f;

    for (int k0 = 0; k0 < DHID; k0 += BK) {
        for (int idx = tid; idx < BM * BK; idx += 256) {
            int kk = idx & (BK - 1);
            int r  = idx >> 4;
            int row = rowBase + r;
            sA[kk][r] = (row < rows) ? g_h[(size_t)row * DHID + (k0 + kk)] : 0.f;
        }
        for (int idx = tid; idx < BK * NH; idx += 256) {
            int kk = idx >> 8;
            int c  = idx & (NH - 1);
            sB[kk][c] = __ldg(&W2[(size_t)(k0 + kk) * NH + c]);
        }
        __syncthreads();
#pragma unroll
        for (int kk = 0; kk < BK; kk++) {
            float a[8], b[8];
            *(float4*)&a[0] = *(const float4*)&sA[kk][ty * 8];
            *(float4*)&a[4] = *(const float4*)&sA[kk][ty * 8 + 4];
            *(float4*)&b[0] = *(const float4*)&sB[kk][colL];
            *(float4*)&b[4] = *(const float4*)&sB[kk][colH];
#pragma unroll
            for (int r = 0; r < 8; r++)
#pragma unroll
                for (int c = 0; c < 8; c++)
                    acc[r][c] = fmaf(a[r], b[c], acc[r][c]);
        }
        __syncthreads();
    }

    float b2c[8];
    *(float4*)&b2c[0] = *(const float4*)&b2[colL];
    *(float4*)&b2c[4] = *(const float4*)&b2[colH];
#pragma unroll
    for (int r = 0; r < 8; r++)
#pragma unroll
        for (int c = 0; c < 8; c++) acc[r][c] += b2c[c];

    const unsigned FULL = 0xffffffffu;
    const unsigned lowmask = (1u << tx) - 1u;

#pragma unroll 1
    for (int r = 0; r < 8; r++) {
        int row = rowBase + ty * 8 + r;     // warp-uniform
        if (row >= rows) continue;
        const float* wrow = wave + (size_t)row * DIN;

        // amps + row amp-sum
        float amp[8];
        *(float4*)&amp[0] = *(const float4*)&wrow[NH + colL];
        *(float4*)&amp[4] = *(const float4*)&wrow[NH + colH];
        float s = 0.f;
#pragma unroll
        for (int j = 0; j < 8; j++) s += amp[j];
#pragma unroll
        for (int o = 16; o; o >>= 1) s += __shfl_xor_sync(FULL, s, o);
        float inv = 1.0f / (s + 1e-8f);

        // gumbel + perturbed keys
        float gub[8];
        *(float4*)&gub[0] = *(const float4*)&gu[(size_t)row * NH + colL];
        *(float4*)&gub[4] = *(const float4*)&gu[(size_t)row * NH + colH];
        unsigned key[8];
        float vbuf[8];
#pragma unroll
        for (int j = 0; j < 8; j++) {
            float t = -logf(gub[j] + 1e-8f);
            float g = -logf(t + 1e-8f);
            float v = acc[r][j] + amp[j] * inv + g;   // TEMP == 1
            vbuf[j] = v;
            key[j] = f2key(v);
        }
        (void)vbuf;

        // exact 128-th largest key via MSB-first radix select (warp-wide)
        unsigned prefix = 0;
        int want = KTOP;
#pragma unroll 1
        for (int bit = 31; bit >= 0; --bit) {
            unsigned tgt = (prefix >> bit) | 1u;
            int c = 0;
#pragma unroll
            for (int j = 0; j < 8; j++) c += ((key[j] >> bit) == tgt);
            c = __reduce_add_sync(FULL, c);
            if (c >= want) prefix |= (1u << bit);
            else           want -= c;
        }
        const unsigned T = prefix;

        // selection with JAX tie-break (lowest index first among equals)
        int mygt = 0;
#pragma unroll
        for (int j = 0; j < 8; j++) mygt += (key[j] > T);
        int need_eq = KTOP - __reduce_add_sync(FULL, mygt);

        unsigned bal[8];
#pragma unroll
        for (int j = 0; j < 8; j++) bal[j] = __ballot_sync(FULL, key[j] == T);

        int low_lower = 0, low_total = 0, high_lower = 0;
#pragma unroll
        for (int j = 0; j < 4; j++) {
            low_lower += __popc(bal[j] & lowmask);
            low_total += __popc(bal[j]);
        }
#pragma unroll
        for (int j = 4; j < 8; j++) high_lower += __popc(bal[j] & lowmask);

        bool sel[8];
        int prev = 0;
#pragma unroll
        for (int j = 0; j < 4; j++) {           // low-half indices tx*4+j
            int e = (bal[j] >> tx) & 1;
            sel[j] = (key[j] > T) || (e && (low_lower + prev) < need_eq);
            prev += e;
        }
        prev = 0;
#pragma unroll
        for (int j = 4; j < 8; j++) {           // high-half indices 128+tx*4+(j-4)
            int e = (bal[j] >> tx) & 1;
            sel[j] = (key[j] > T) || (e && (low_total + high_lower + prev) < need_eq);
            prev += e;
        }

        // masked write: out = [freqs*m, amps*m, phases*m]
        float fr[8], ph[8];
        *(float4*)&fr[0] = *(const float4*)&wrow[colL];
        *(float4*)&fr[4] = *(const float4*)&wrow[colH];
        *(float4*)&ph[0] = *(const float4*)&wrow[2 * NH + colL];
        *(float4*)&ph[4] = *(const float4*)&wrow[2 * NH + colH];

        float of[8], oa[8], op[8];
#pragma unroll
        for (int j = 0; j < 8; j++) {
            float m = sel[j] ? 1.0f : 0.0f;
            of[j] = fr[j] * m;
            oa[j] = amp[j] * m;
            op[j] = ph[j] * m;
        }
        float* orow = out + (size_t)row * DIN;
        *(float4*)&orow[colL]          = *(float4*)&of[0];
        *(float4*)&orow[colH]          = *(float4*)&of[4];
        *(float4*)&orow[NH + colL]     = *(float4*)&oa[0];
        *(float4*)&orow[NH + colH]     = *(float4*)&oa[4];
        *(float4*)&orow[2 * NH + colL] = *(float4*)&op[0];
        *(float4*)&orow[2 * NH + colH] = *(float4*)&op[4];
    }
}

// ---------------------------------------------------------------------------
extern "C" void kernel_launch(void* const* d_in, const int* in_sizes, int n_in,
                              void* d_out, int out_size)
{
    const float* wave = (const float*)d_in[0];
    const float* gu   = (const float*)d_in[1];
    const float* W1   = (const float*)d_in[2];
    const float* b1   = (const float*)d_in[3];
    const float* lng  = (const float*)d_in[4];
    const float* lnb  = (const float*)d_in[5];
    const float* W2   = (const float*)d_in[6];
    const float* b2   = (const float*)d_in[7];
    float* out = (float*)d_out;

    int rows = in_sizes[0] / DIN;           // 32768
    int nb   = (rows + BM - 1) / BM;        // 512

    k_mlp1<<<nb, 384>>>(wave, W1, b1, lng, lnb, rows);
    k_mlp2<<<nb, 256>>>(W2, b2, wave, gu, out, rows);
}

// round 11
// speedup vs baseline: 1.2709x; 1.2701x over previous
#include <cuda_runtime.h>
#include <cstdint>

#define DIN   768
#define DHID  384
#define NH    256
#define KTOP  128
#define BM    64      // rows per CTA
#define BK    8       // k-chunk (double-buffered)

// Scratch for h = silu(LN(wave@W1+b1)) : 32768 x 384 fp32 (48 MiB, proven size)
__device__ float g_h[8 * 4096 * DHID];

static __device__ __forceinline__ unsigned f2key(float f) {
    unsigned u = __float_as_uint(f);
    return (u & 0x80000000u) ? ~u : (u | 0x80000000u);  // monotone float->uint
}

// ---------------------------------------------------------------------------
// Kernel 1: h = silu(layernorm(wave @ W1 + b1))  -> g_h
// CTA: 64 rows x 384 cols, 384 threads, 8x8 thread tiles, double-buffered BK=8.
// Thread (ty,tx): rows ty*8..+7, cols {tx*4..+3} and {192+tx*4..+3}
// ---------------------------------------------------------------------------
__global__ void __launch_bounds__(384) k_mlp1(
    const float* __restrict__ wave, const float* __restrict__ W1,
    const float* __restrict__ b1,   const float* __restrict__ lng,
    const float* __restrict__ lnb,  int rows)
{
    __shared__ float sA[2][BK][BM];      // [buf][k][row]
    __shared__ float sB[2][BK][DHID];    // [buf][k][col]; buf0 reused as reduction buf
    __shared__ float sMu[BM];
    __shared__ float sRs[BM];

    const int tid  = threadIdx.x;
    const int ty   = tid / 48;
    const int tx   = tid - ty * 48;
    const int colL = tx * 4;
    const int colH = 192 + tx * 4;
    const int rowBase = blockIdx.x * BM;
    const int NCH = DIN / BK;            // 96

    float acc[8][8];
#pragma unroll
    for (int r = 0; r < 8; r++)
#pragma unroll
        for (int c = 0; c < 8; c++) acc[r][c] = 0.f;

    // --- prologue: stage chunk 0 ---
#pragma unroll
    for (int it = 0; it < 2; it++) {
        int idx = tid + it * 384;
        if (idx < BM * BK) {
            int kk = idx & (BK - 1), r = idx >> 3;
            sA[0][kk][r] = (rowBase + r < rows)
                ? __ldg(&wave[(size_t)(rowBase + r) * DIN + kk]) : 0.f;
        }
    }
#pragma unroll
    for (int it = 0; it < BK; it++)      // kk == it, c == tid
        sB[0][it][tid] = __ldg(&W1[(size_t)it * DHID + tid]);
    __syncthreads();

    int buf = 0;
    for (int ch = 0; ch < NCH; ch++) {
        const bool has = (ch + 1) < NCH;
        const int k0n = (ch + 1) * BK;
        float pa[2], pb[8];
        // prefetch chunk ch+1 into registers (latency hidden under compute)
        if (has) {
#pragma unroll
            for (int it = 0; it < 2; it++) {
                int idx = tid + it * 384;
                pa[it] = 0.f;
                if (idx < BM * BK) {
                    int kk = idx & (BK - 1), r = idx >> 3;
                    if (rowBase + r < rows)
                        pa[it] = __ldg(&wave[(size_t)(rowBase + r) * DIN + k0n + kk]);
                }
            }
#pragma unroll
            for (int it = 0; it < BK; it++)
                pb[it] = __ldg(&W1[(size_t)(k0n + it) * DHID + tid]);
        }
        // compute on current buffer
#pragma unroll
        for (int kk = 0; kk < BK; kk++) {
            float a[8], b[8];
            *(float4*)&a[0] = *(const float4*)&sA[buf][kk][ty * 8];
            *(float4*)&a[4] = *(const float4*)&sA[buf][kk][ty * 8 + 4];
            *(float4*)&b[0] = *(const float4*)&sB[buf][kk][colL];
            *(float4*)&b[4] = *(const float4*)&sB[buf][kk][colH];
#pragma unroll
            for (int r = 0; r < 8; r++)
#pragma unroll
                for (int c = 0; c < 8; c++)
                    acc[r][c] = fmaf(a[r], b[c], acc[r][c]);
        }
        // store prefetched chunk into the other buffer (safe: last read of it
        // completed before the sync that ended the previous iteration)
        if (has) {
#pragma unroll
            for (int it = 0; it < 2; it++) {
                int idx = tid + it * 384;
                if (idx < BM * BK) {
                    int kk = idx & (BK - 1), r = idx >> 3;
                    sA[buf ^ 1][kk][r] = pa[it];
                }
            }
#pragma unroll
            for (int it = 0; it < BK; it++)
                sB[buf ^ 1][it][tid] = pb[it];
        }
        __syncthreads();
        buf ^= 1;
    }

    // Per-thread column params
    float bc[8], gc[8], bb[8];
    *(float4*)&bc[0] = *(const float4*)&b1[colL];
    *(float4*)&bc[4] = *(const float4*)&b1[colH];
    *(float4*)&gc[0] = *(const float4*)&lng[colL];
    *(float4*)&gc[4] = *(const float4*)&lng[colH];
    *(float4*)&bb[0] = *(const float4*)&lnb[colL];
    *(float4*)&bb[4] = *(const float4*)&lnb[colH];

#pragma unroll
    for (int r = 0; r < 8; r++)
#pragma unroll
        for (int c = 0; c < 8; c++) acc[r][c] += bc[c];

    float* red = &sB[0][0][0];   // 64 x 48 (stride 49) partial sums

    // Pass 1: mean
#pragma unroll
    for (int r = 0; r < 8; r++) {
        float s = 0.f;
#pragma unroll
        for (int c = 0; c < 8; c++) s += acc[r][c];
        red[(ty * 8 + r) * 49 + tx] = s;
    }
    __syncthreads();
    if (tid < BM) {
        float s = 0.f;
        for (int i = 0; i < 48; i++) s += red[tid * 49 + i];
        sMu[tid] = s * (1.0f / DHID);
    }
    __syncthreads();
    float mu[8];
#pragma unroll
    for (int r = 0; r < 8; r++) mu[r] = sMu[ty * 8 + r];

    // Pass 2: variance
#pragma unroll
    for (int r = 0; r < 8; r++) {
        float s = 0.f;
#pragma unroll
        for (int c = 0; c < 8; c++) {
            float dd = acc[r][c] - mu[r];
            s = fmaf(dd, dd, s);
        }
        red[(ty * 8 + r) * 49 + tx] = s;
    }
    __syncthreads();
    if (tid < BM) {
        float s = 0.f;
        for (int i = 0; i < 48; i++) s += red[tid * 49 + i];
        sRs[tid] = rsqrtf(s * (1.0f / DHID) + 1e-5f);
    }
    __syncthreads();

#pragma unroll
    for (int r = 0; r < 8; r++) {
        int row = rowBase + ty * 8 + r;
        if (row >= rows) continue;
        float rs = sRs[ty * 8 + r];
        float o[8];
#pragma unroll
        for (int c = 0; c < 8; c++) {
            float x = (acc[r][c] - mu[r]) * rs * gc[c] + bb[c];
            o[c] = x / (1.0f + expf(-x));   // silu
        }
        float* dst = &g_h[(size_t)row * DHID];
        *(float4*)&dst[colL] = *(float4*)&o[0];
        *(float4*)&dst[colH] = *(float4*)&o[4];
    }
}

// ---------------------------------------------------------------------------
// Kernel 2: scores = h @ W2 + b2, fused perturb + exact top-128 + masked write
// CTA: 64 rows x 256 cols, 256 threads, double-buffered BK=8.
// warp == ty owns rows ty*8..+7; thread cols {tx*4..+3} and {128+tx*4..+3}
// ---------------------------------------------------------------------------
__global__ void __launch_bounds__(256) k_mlp2(
    const float* __restrict__ W2,  const float* __restrict__ b2,
    const float* __restrict__ wave, const float* __restrict__ gu,
    float* __restrict__ out, int rows)
{
    __shared__ float sA[2][BK][BM];
    __shared__ float sB[2][BK][NH];

    const int tid  = threadIdx.x;
    const int ty   = tid >> 5;      // warp id
    const int tx   = tid & 31;      // lane id
    const int colL = tx * 4;
    const int colH = 128 + tx * 4;
    const int rowBase = blockIdx.x * BM;
    const int NCH = DHID / BK;      // 48

    float acc[8][8];
#pragma unroll
    for (int r = 0; r < 8; r++)
#pragma unroll
        for (int c = 0; c < 8; c++) acc[r][c] = 0.f;

    // --- prologue: stage chunk 0 ---
#pragma unroll
    for (int it = 0; it < 2; it++) {
        int idx = tid + it * 256;
        int kk = idx & (BK - 1), r = idx >> 3;
        sA[0][kk][r] = (rowBase + r < rows)
            ? g_h[(size_t)(rowBase + r) * DHID + kk] : 0.f;
    }
#pragma unroll
    for (int it = 0; it < BK; it++)      // kk == it, c == tid
        sB[0][it][tid] = __ldg(&W2[(size_t)it * NH + tid]);
    __syncthreads();

    int buf = 0;
    for (int ch = 0; ch < NCH; ch++) {
        const bool has = (ch + 1) < NCH;
        const int k0n = (ch + 1) * BK;
        float pa[2], pb[8];
        if (has) {
#pragma unroll
            for (int it = 0; it < 2; it++) {
                int idx = tid + it * 256;
                int kk = idx & (BK - 1), r = idx >> 3;
                pa[it] = (rowBase + r < rows)
                    ? g_h[(size_t)(rowBase + r) * DHID + k0n + kk] : 0.f;
            }
#pragma unroll
            for (int it = 0; it < BK; it++)
                pb[it] = __ldg(&W2[(size_t)(k0n + it) * NH + tid]);
        }
#pragma unroll
        for (int kk = 0; kk < BK; kk++) {
            float a[8], b[8];
            *(float4*)&a[0] = *(const float4*)&sA[buf][kk][ty * 8];
            *(float4*)&a[4] = *(const float4*)&sA[buf][kk][ty * 8 + 4];
            *(float4*)&b[0] = *(const float4*)&sB[buf][kk][colL];
            *(float4*)&b[4] = *(const float4*)&sB[buf][kk][colH];
#pragma unroll
            for (int r = 0; r < 8; r++)
#pragma unroll
                for (int c = 0; c < 8; c++)
                    acc[r][c] = fmaf(a[r], b[c], acc[r][c]);
        }
        if (has) {
#pragma unroll
            for (int it = 0; it < 2; it++) {
                int idx = tid + it * 256;
                int kk = idx & (BK - 1), r = idx >> 3;
                sA[buf ^ 1][kk][r] = pa[it];
            }
#pragma unroll
            for (int it = 0; it < BK; it++)
                sB[buf ^ 1][it][tid] = pb[it];
        }
        __syncthreads();
        buf ^= 1;
    }

    float b2c[8];
    *(float4*)&b2c[0] = *(const float4*)&b2[colL];
    *(float4*)&b2c[4] = *(const float4*)&b2[colH];
#pragma unroll
    for (int r = 0; r < 8; r++)
#pragma unroll
        for (int c = 0; c < 8; c++) acc[r][c] += b2c[c];

    const unsigned FULL = 0xffffffffu;
    const unsigned lowmask = (1u << tx) - 1u;

#pragma unroll 1
    for (int r = 0; r < 8; r++) {
        int row = rowBase + ty * 8 + r;     // warp-uniform
        if (row >= rows) continue;
        const float* wrow = wave + (size_t)row * DIN;

        // amps + row amp-sum
        float amp[8];
        *(float4*)&amp[0] = *(const float4*)&wrow[NH + colL];
        *(float4*)&amp[4] = *(const float4*)&wrow[NH + colH];
        float s = 0.f;
#pragma unroll
        for (int j = 0; j < 8; j++) s += amp[j];
#pragma unroll
        for (int o = 16; o; o >>= 1) s += __shfl_xor_sync(FULL, s, o);
        float inv = 1.0f / (s + 1e-8f);

        // gumbel + perturbed keys
        float gub[8];
        *(float4*)&gub[0] = *(const float4*)&gu[(size_t)row * NH + colL];
        *(float4*)&gub[4] = *(const float4*)&gu[(size_t)row * NH + colH];
        unsigned key[8];
#pragma unroll
        for (int j = 0; j < 8; j++) {
            float t = -logf(gub[j] + 1e-8f);
            float g = -logf(t + 1e-8f);
            key[j] = f2key(acc[r][j] + amp[j] * inv + g);   // TEMP == 1
        }

        // exact 128-th largest key via MSB-first radix select (warp-wide)
        unsigned prefix = 0;
        int want = KTOP;
#pragma unroll 1
        for (int bit = 31; bit >= 0; --bit) {
            unsigned tgt = (prefix >> bit) | 1u;
            int c = 0;
#pragma unroll
            for (int j = 0; j < 8; j++) c += ((key[j] >> bit) == tgt);
            c = __reduce_add_sync(FULL, c);
            if (c >= want) prefix |= (1u << bit);
            else           want -= c;
        }
        const unsigned T = prefix;

        // selection with JAX tie-break (lowest index first among equals)
        int mygt = 0;
#pragma unroll
        for (int j = 0; j < 8; j++) mygt += (key[j] > T);
        int need_eq = KTOP - __reduce_add_sync(FULL, mygt);

        unsigned bal[8];
#pragma unroll
        for (int j = 0; j < 8; j++) bal[j] = __ballot_sync(FULL, key[j] == T);

        int low_lower = 0, low_total = 0, high_lower = 0;
#pragma unroll
        for (int j = 0; j < 4; j++) {
            low_lower += __popc(bal[j] & lowmask);
            low_total += __popc(bal[j]);
        }
#pragma unroll
        for (int j = 4; j < 8; j++) high_lower += __popc(bal[j] & lowmask);

        bool sel[8];
        int prev = 0;
#pragma unroll
        for (int j = 0; j < 4; j++) {           // low-half indices tx*4+j
            int e = (bal[j] >> tx) & 1;
            sel[j] = (key[j] > T) || (e && (low_lower + prev) < need_eq);
            prev += e;
        }
        prev = 0;
#pragma unroll
        for (int j = 4; j < 8; j++) {           // high-half indices 128+tx*4+(j-4)
            int e = (bal[j] >> tx) & 1;
            sel[j] = (key[j] > T) || (e && (low_total + high_lower + prev) < need_eq);
            prev += e;
        }

        // masked write: out = [freqs*m, amps*m, phases*m]
        float fr[8], ph[8];
        *(float4*)&fr[0] = *(const float4*)&wrow[colL];
        *(float4*)&fr[4] = *(const float4*)&wrow[colH];
        *(float4*)&ph[0] = *(const float4*)&wrow[2 * NH + colL];
        *(float4*)&ph[4] = *(const float4*)&wrow[2 * NH + colH];

        float of[8], oa[8], op[8];
#pragma unroll
        for (int j = 0; j < 8; j++) {
            float m = sel[j] ? 1.0f : 0.0f;
            of[j] = fr[j] * m;
            oa[j] = amp[j] * m;
            op[j] = ph[j] * m;
        }
        float* orow = out + (size_t)row * DIN;
        *(float4*)&orow[colL]          = *(float4*)&of[0];
        *(float4*)&orow[colH]          = *(float4*)&of[4];
        *(float4*)&orow[NH + colL]     = *(float4*)&oa[0];
        *(float4*)&orow[NH + colH]     = *(float4*)&oa[4];
        *(float4*)&orow[2 * NH + colL] = *(float4*)&op[0];
        *(float4*)&orow[2 * NH + colH] = *(float4*)&op[4];
    }
}

// ---------------------------------------------------------------------------
extern "C" void kernel_launch(void* const* d_in, const int* in_sizes, int n_in,
                              void* d_out, int out_size)
{
    const float* wave = (const float*)d_in[0];
    const float* gu   = (const float*)d_in[1];
    const float* W1   = (const float*)d_in[2];
    const float* b1   = (const float*)d_in[3];
    const float* lng  = (const float*)d_in[4];
    const float* lnb  = (const float*)d_in[5];
    const float* W2   = (const float*)d_in[6];
    const float* b2   = (const float*)d_in[7];
    float* out = (float*)d_out;

    int rows = in_sizes[0] / DIN;           // 32768
    int nb   = (rows + BM - 1) / BM;        // 512

    k_mlp1<<<nb, 384>>>(wave, W1, b1, lng, lnb, rows);
    k_mlp2<<<nb, 256>>>(W2, b2, wave, gu, out, rows);
}